// round 9
// baseline (speedup 1.0000x reference)
#include <cuda_runtime.h>
#include <stdint.h>

#define N_NODES 100000
#define F4      16                       // 64 floats = 16 float4 per node
#define NTOT4   (N_NODES * F4)
#define E_MAX   2000000                  // CSR src buffer capacity (E = 1.6M)
#define SCAN_T  1024
#define SCHUNK  ((N_NODES + SCAN_T - 1) / SCAN_T)   // 98 nodes per thread

// Scratch (no device allocation allowed -> __device__ globals)
__device__ int g_counts[N_NODES];        // in-degree
__device__ int g_row[N_NODES];           // CSR row start (exclusive prefix)
__device__ int g_cursor[N_NODES];        // scatter cursor
__device__ int g_srcbuf[E_MAX];          // src node id per edge, grouped by dst
__device__ int g_idx_is64;               // 1 = int64 indices, 0 = int32

// ---------------------------------------------------------------------------
// A: zero counts + dtype detect (64 batched loads, no serial break chain).
// int32 data read as int64 packs two indices: value >= 2^32 unless the high
// index is 0 (p = 1e-5 per word) -> 64 words decide with certainty ~1-1e-320.
// ---------------------------------------------------------------------------
__global__ void prep_kernel(const long long* __restrict__ ei, int E) {
    int i = blockIdx.x * blockDim.x + threadIdx.x;
    if (i < N_NODES) g_counts[i] = 0;
    if (blockIdx.x == 0 && threadIdx.x == 0) {
        int n = E < 64 ? E : 64;
        int ok = 1;
        #pragma unroll
        for (int k = 0; k < 64; k++) {
            if (k < n) {
                long long v = ei[k];
                if (v < 0 || v >= N_NODES) ok = 0;
            }
        }
        g_idx_is64 = ok;
    }
}

__device__ __forceinline__ long long load_idx(const void* eiv, long long pos) {
    if (g_idx_is64) return ((const long long*)eiv)[pos];
    return (long long)((const int*)eiv)[pos];
}

// ---------------------------------------------------------------------------
// B: in-degree histogram over dst
// ---------------------------------------------------------------------------
__global__ void hist_kernel(const void* __restrict__ eiv, int E) {
    int e = blockIdx.x * blockDim.x + threadIdx.x;
    if (e >= E) return;
    long long d = load_idx(eiv, (long long)E + e);
    if ((unsigned long long)d < (unsigned long long)N_NODES)
        atomicAdd(&g_counts[(int)d], 1);
}

// ---------------------------------------------------------------------------
// C: full exclusive prefix sum in ONE single-block kernel.
//    1024 threads x 98-node chunks: chunk sums -> Hillis-Steele block scan
//    -> sequential per-chunk writeback of g_row and g_cursor.
//    (Replaces the 3-launch scan; the old 1-thread scan2 alone was 8.3 us.)
// ---------------------------------------------------------------------------
__global__ void scan_kernel() {
    __shared__ int ssum[SCAN_T];
    int t = threadIdx.x;
    int start = t * SCHUNK;

    int sum = 0;
    #pragma unroll 4
    for (int i = 0; i < SCHUNK; i++) {
        int idx = start + i;
        if (idx < N_NODES) sum += g_counts[idx];
    }
    ssum[t] = sum;
    __syncthreads();

    #pragma unroll
    for (int off = 1; off < SCAN_T; off <<= 1) {
        int x = (t >= off) ? ssum[t - off] : 0;
        __syncthreads();
        ssum[t] += x;
        __syncthreads();
    }

    int run = ssum[t] - sum;   // exclusive base of this thread's chunk
    #pragma unroll 4
    for (int i = 0; i < SCHUNK; i++) {
        int idx = start + i;
        if (idx < N_NODES) {
            int c = g_counts[idx];     // L2 hit
            g_row[idx] = run;
            g_cursor[idx] = run;
            run += c;
        }
    }
}

// ---------------------------------------------------------------------------
// D: scatter src ids into CSR buckets
// ---------------------------------------------------------------------------
__global__ void scatter_kernel(const void* __restrict__ eiv, int E) {
    int e = blockIdx.x * blockDim.x + threadIdx.x;
    if (e >= E) return;
    long long s = load_idx(eiv, e);
    long long d = load_idx(eiv, (long long)E + e);
    if ((unsigned long long)s >= (unsigned long long)N_NODES ||
        (unsigned long long)d >= (unsigned long long)N_NODES) return;
    int pos = atomicAdd(&g_cursor[(int)d], 1);
    if (pos >= 0 && pos < E_MAX) g_srcbuf[pos] = (int)s;
}

// ---------------------------------------------------------------------------
// E: aggregate + finalize, fused. 16 lanes per node, lane c owns float4 #c.
// Batch-load 16 src ids coalesced, shfl-broadcast within the 16-lane segment.
// Fast path for full 16-edge batches (no per-iteration bounds checks; the
// unrolled LDG chain gives MLP=16 into the L2-resident node table).
//   out[i] = cnt>0 ? 2*nf[i] + sum_src/cnt : nf[i]
// Output written exactly once -> no zero pass, no atomics, no final pass.
// ---------------------------------------------------------------------------
__global__ void aggregate_kernel(const float4* __restrict__ nf,
                                 float4* __restrict__ out) {
    int t = blockIdx.x * blockDim.x + threadIdx.x;
    int node = t >> 4;
    int c    = t & 15;
    if (node >= N_NODES) return;
    unsigned gmask = 0xFFFFu << (threadIdx.x & 16);

    int row = g_row[node];
    int cnt = g_counts[node];

    float4 acc = make_float4(0.f, 0.f, 0.f, 0.f);
    int base = 0;
    int nfull = cnt & ~15;          // full 16-edge batches
    for (; base < nfull; base += 16) {
        int id = g_srcbuf[row + base + c];            // coalesced 64B / group
        #pragma unroll 4
        for (int j = 0; j < 16; j++) {
            int s = __shfl_sync(gmask, id, j, 16);
            float4 v = __ldg(&nf[(long long)s * F4 + c]);
            acc.x += v.x; acc.y += v.y; acc.z += v.z; acc.w += v.w;
        }
    }
    int m = cnt - base;             // 0..15 tail
    if (m > 0) {
        int k  = base + c;
        int id = (k < cnt) ? g_srcbuf[row + k] : 0;
        for (int j = 0; j < m; j++) {
            int s = __shfl_sync(gmask, id, j, 16);
            float4 v = __ldg(&nf[(long long)s * F4 + c]);
            acc.x += v.x; acc.y += v.y; acc.z += v.z; acc.w += v.w;
        }
    }

    float4 f = nf[(long long)node * F4 + c];
    float4 r;
    if (cnt > 0) {
        float inv = 1.0f / (float)cnt;
        r.x = 2.0f * f.x + acc.x * inv;
        r.y = 2.0f * f.y + acc.y * inv;
        r.z = 2.0f * f.z + acc.z * inv;
        r.w = 2.0f * f.w + acc.w * inv;
    } else {
        r = f;
    }
    out[(long long)node * F4 + c] = r;
}

// ---------------------------------------------------------------------------
// Fallback path (E > E_MAX): direct-RED design (known correct from R6).
// ---------------------------------------------------------------------------
__global__ void fb_zero_kernel(float4* __restrict__ out) {
    int i = blockIdx.x * blockDim.x + threadIdx.x;
    if (i < NTOT4) out[i] = make_float4(0.f, 0.f, 0.f, 0.f);
}

__global__ void fb_edge_kernel(const float4* __restrict__ nf,
                               const void*   __restrict__ eiv,
                               float4*       __restrict__ out, int E) {
    long long t = (long long)blockIdx.x * blockDim.x + threadIdx.x;
    long long e = t >> 4;
    int c    = (int)(t & 15);
    int lane = threadIdx.x & 31;
    bool valid = (e < E);
    long long ec = valid ? e : (long long)(E - 1);
    long long s = 0, d = 0;
    if ((lane & 15) == 0) {
        s = load_idx(eiv, ec);
        d = load_idx(eiv, (long long)E + ec);
    }
    int leader = lane & 16;
    s = __shfl_sync(0xffffffffu, s, leader);
    d = __shfl_sync(0xffffffffu, d, leader);
    if (!valid) return;
    if ((unsigned long long)s >= (unsigned long long)N_NODES ||
        (unsigned long long)d >= (unsigned long long)N_NODES) return;
    if (c == 0) atomicAdd(&g_counts[(int)d], 1);
    float4 v = __ldg(&nf[s * F4 + c]);
    float4* p = &out[d * F4 + c];
    asm volatile("red.global.add.v4.f32 [%0], {%1, %2, %3, %4};"
                 :: "l"(p), "f"(v.x), "f"(v.y), "f"(v.z), "f"(v.w) : "memory");
}

__global__ void fb_final_kernel(const float4* __restrict__ nf,
                                float4* __restrict__ out) {
    int i = blockIdx.x * blockDim.x + threadIdx.x;
    if (i >= NTOT4) return;
    int cnt = g_counts[i >> 4];
    float4 f = nf[i];
    float4 r;
    if (cnt > 0) {
        float inv = 1.0f / (float)cnt;
        float4 a = out[i];
        r.x = 2.0f * f.x + a.x * inv;
        r.y = 2.0f * f.y + a.y * inv;
        r.z = 2.0f * f.z + a.z * inv;
        r.w = 2.0f * f.w + a.w * inv;
    } else r = f;
    out[i] = r;
}

// ---------------------------------------------------------------------------
extern "C" void kernel_launch(void* const* d_in, const int* in_sizes, int n_in,
                              void* d_out, int out_size) {
    // Role selection by element count (dtype-independent):
    //   node_features: 6,400,000 elements (== out_size); edge_index: 2*E
    int nf_i = (in_sizes[0] == out_size) ? 0 : 1;
    int ei_i = 1 - nf_i;

    const float4* nf  = (const float4*)d_in[nf_i];
    const void*   ei  = d_in[ei_i];
    float4*       out = (float4*)d_out;
    int E = in_sizes[ei_i] / 2;

    prep_kernel<<<(N_NODES + 255) / 256, 256>>>((const long long*)ei, E);

    if (E <= E_MAX) {
        int eb = (E + 255) / 256;
        hist_kernel<<<eb, 256>>>(ei, E);
        scan_kernel<<<1, SCAN_T>>>();
        scatter_kernel<<<eb, 256>>>(ei, E);
        aggregate_kernel<<<(NTOT4 + 255) / 256, 256>>>(nf, out);
    } else {
        fb_zero_kernel<<<(NTOT4 + 255) / 256, 256>>>(out);
        long long total = (long long)E * 16;
        fb_edge_kernel<<<(int)((total + 255) / 256), 256>>>(nf, ei, out, E);
        fb_final_kernel<<<(NTOT4 + 255) / 256, 256>>>(nf, out);
    }
}

// round 13
// speedup vs baseline: 2.9508x; 2.9508x over previous
#include <cuda_runtime.h>
#include <stdint.h>

#define N_NODES 100000
#define F4      16                       // 64 floats = 16 float4 per node
#define NTOT4   (N_NODES * F4)
#define E_MAX   2000000                  // CSR src buffer capacity (E = 1.6M)
#define SCAN_B  1024
#define NBLK    ((N_NODES + SCAN_B - 1) / SCAN_B)   // 98

// Scratch (no device allocation allowed -> __device__ globals)
__device__ int g_counts[N_NODES];        // in-degree
__device__ int g_row[N_NODES];           // CSR row start (exclusive prefix)
__device__ int g_cursor[N_NODES];        // scatter cursor
__device__ int g_srcbuf[E_MAX];          // src node id per edge, grouped by dst
__device__ int g_blocksum[NBLK];
__device__ int g_idx_is64;               // 1 = int64 indices, 0 = int32

// ---------------------------------------------------------------------------
// A: zero counts + dtype detect (64 batched loads, no serial break chain).
// int32 data read as int64 packs two indices: value >= 2^32 unless the high
// index is 0 (p = 1e-5 per word) -> 64 words decide essentially surely.
// ---------------------------------------------------------------------------
__global__ void prep_kernel(const long long* __restrict__ ei, int E) {
    int i = blockIdx.x * blockDim.x + threadIdx.x;
    if (i < N_NODES) g_counts[i] = 0;
    if (blockIdx.x == 0 && threadIdx.x == 0) {
        int n = E < 64 ? E : 64;
        int ok = 1;
        #pragma unroll
        for (int k = 0; k < 64; k++) {
            if (k < n) {
                long long v = ei[k];
                if (v < 0 || v >= N_NODES) ok = 0;
            }
        }
        g_idx_is64 = ok;
    }
}

__device__ __forceinline__ long long load_idx(const void* eiv, long long pos) {
    if (g_idx_is64) return ((const long long*)eiv)[pos];
    return (long long)((const int*)eiv)[pos];
}

// ---------------------------------------------------------------------------
// B: in-degree histogram over dst
// ---------------------------------------------------------------------------
__global__ void hist_kernel(const void* __restrict__ eiv, int E) {
    int e = blockIdx.x * blockDim.x + threadIdx.x;
    if (e >= E) return;
    long long d = load_idx(eiv, (long long)E + e);
    if ((unsigned long long)d < (unsigned long long)N_NODES)
        atomicAdd(&g_counts[(int)d], 1);
}

// ---------------------------------------------------------------------------
// C1: per-block exclusive scan of counts -> g_row (block-local) + block sums.
//     98 blocks: the full chip works in parallel (the R9 one-block scan bound
//     the whole pass to a single SM's LSU -- never again).
// ---------------------------------------------------------------------------
__global__ void scanA_kernel() {
    __shared__ int sm[SCAN_B];
    int t = threadIdx.x;
    int i = blockIdx.x * SCAN_B + t;
    int v = (i < N_NODES) ? g_counts[i] : 0;
    sm[t] = v;
    __syncthreads();
    #pragma unroll
    for (int off = 1; off < SCAN_B; off <<= 1) {
        int x = (t >= off) ? sm[t - off] : 0;
        __syncthreads();
        sm[t] += x;
        __syncthreads();
    }
    if (i < N_NODES) g_row[i] = sm[t] - v;            // exclusive within block
    if (t == SCAN_B - 1) g_blocksum[blockIdx.x] = sm[t];
}

// ---------------------------------------------------------------------------
// C2: each block tree-reduces blocksum[0..blockIdx) (<=98 ints, in smem) to
//     get its global offset, then writes final g_row/g_cursor. Replaces the
//     old serial scan2 (8.3 us) + scan3 with one parallel launch.
// ---------------------------------------------------------------------------
__global__ void scanB_kernel() {
    __shared__ int sb[128];
    int t = threadIdx.x;
    if (t < 128) sb[t] = (t < blockIdx.x && t < NBLK) ? g_blocksum[t] : 0;
    __syncthreads();
    #pragma unroll
    for (int off = 64; off > 0; off >>= 1) {
        if (t < off) sb[t] += sb[t + off];
        __syncthreads();
    }
    int offset = sb[0];
    int i = blockIdx.x * SCAN_B + t;
    if (i < N_NODES) {
        int r = g_row[i] + offset;
        g_row[i] = r;
        g_cursor[i] = r;
    }
}

// ---------------------------------------------------------------------------
// D: scatter src ids into CSR buckets
// ---------------------------------------------------------------------------
__global__ void scatter_kernel(const void* __restrict__ eiv, int E) {
    int e = blockIdx.x * blockDim.x + threadIdx.x;
    if (e >= E) return;
    long long s = load_idx(eiv, e);
    long long d = load_idx(eiv, (long long)E + e);
    if ((unsigned long long)s >= (unsigned long long)N_NODES ||
        (unsigned long long)d >= (unsigned long long)N_NODES) return;
    int pos = atomicAdd(&g_cursor[(int)d], 1);
    if (pos >= 0 && pos < E_MAX) g_srcbuf[pos] = (int)s;
}

// ---------------------------------------------------------------------------
// E: aggregate + finalize, fused. 16 lanes per node, lane c owns float4 #c.
// Batch-load 16 src ids coalesced, shfl-broadcast within the 16-lane segment.
// Fast path for full 16-edge batches; unrolled LDG chain raises MLP into the
// L2-resident node table.
//   out[i] = cnt>0 ? 2*nf[i] + sum_src/cnt : nf[i]
// Output written exactly once -> no zero pass, no atomics, no final pass.
// ---------------------------------------------------------------------------
__global__ void aggregate_kernel(const float4* __restrict__ nf,
                                 float4* __restrict__ out) {
    int t = blockIdx.x * blockDim.x + threadIdx.x;
    int node = t >> 4;
    int c    = t & 15;
    if (node >= N_NODES) return;
    unsigned gmask = 0xFFFFu << (threadIdx.x & 16);

    int row = g_row[node];
    int cnt = g_counts[node];

    float4 acc = make_float4(0.f, 0.f, 0.f, 0.f);
    int base = 0;
    int nfull = cnt & ~15;          // full 16-edge batches
    for (; base < nfull; base += 16) {
        int id = g_srcbuf[row + base + c];            // coalesced 64B / group
        #pragma unroll 4
        for (int j = 0; j < 16; j++) {
            int s = __shfl_sync(gmask, id, j, 16);
            float4 v = __ldg(&nf[(long long)s * F4 + c]);
            acc.x += v.x; acc.y += v.y; acc.z += v.z; acc.w += v.w;
        }
    }
    int m = cnt - base;             // 0..15 tail
    if (m > 0) {
        int k  = base + c;
        int id = (k < cnt) ? g_srcbuf[row + k] : 0;
        for (int j = 0; j < m; j++) {
            int s = __shfl_sync(gmask, id, j, 16);
            float4 v = __ldg(&nf[(long long)s * F4 + c]);
            acc.x += v.x; acc.y += v.y; acc.z += v.z; acc.w += v.w;
        }
    }

    float4 f = nf[(long long)node * F4 + c];
    float4 r;
    if (cnt > 0) {
        float inv = 1.0f / (float)cnt;
        r.x = 2.0f * f.x + acc.x * inv;
        r.y = 2.0f * f.y + acc.y * inv;
        r.z = 2.0f * f.z + acc.z * inv;
        r.w = 2.0f * f.w + acc.w * inv;
    } else {
        r = f;
    }
    out[(long long)node * F4 + c] = r;
}

// ---------------------------------------------------------------------------
// Fallback path (E > E_MAX): direct-RED design (known correct from R6).
// ---------------------------------------------------------------------------
__global__ void fb_zero_kernel(float4* __restrict__ out) {
    int i = blockIdx.x * blockDim.x + threadIdx.x;
    if (i < NTOT4) out[i] = make_float4(0.f, 0.f, 0.f, 0.f);
}

__global__ void fb_edge_kernel(const float4* __restrict__ nf,
                               const void*   __restrict__ eiv,
                               float4*       __restrict__ out, int E) {
    long long t = (long long)blockIdx.x * blockDim.x + threadIdx.x;
    long long e = t >> 4;
    int c    = (int)(t & 15);
    int lane = threadIdx.x & 31;
    bool valid = (e < E);
    long long ec = valid ? e : (long long)(E - 1);
    long long s = 0, d = 0;
    if ((lane & 15) == 0) {
        s = load_idx(eiv, ec);
        d = load_idx(eiv, (long long)E + ec);
    }
    int leader = lane & 16;
    s = __shfl_sync(0xffffffffu, s, leader);
    d = __shfl_sync(0xffffffffu, d, leader);
    if (!valid) return;
    if ((unsigned long long)s >= (unsigned long long)N_NODES ||
        (unsigned long long)d >= (unsigned long long)N_NODES) return;
    if (c == 0) atomicAdd(&g_counts[(int)d], 1);
    float4 v = __ldg(&nf[s * F4 + c]);
    float4* p = &out[d * F4 + c];
    asm volatile("red.global.add.v4.f32 [%0], {%1, %2, %3, %4};"
                 :: "l"(p), "f"(v.x), "f"(v.y), "f"(v.z), "f"(v.w) : "memory");
}

__global__ void fb_final_kernel(const float4* __restrict__ nf,
                                float4* __restrict__ out) {
    int i = blockIdx.x * blockDim.x + threadIdx.x;
    if (i >= NTOT4) return;
    int cnt = g_counts[i >> 4];
    float4 f = nf[i];
    float4 r;
    if (cnt > 0) {
        float inv = 1.0f / (float)cnt;
        float4 a = out[i];
        r.x = 2.0f * f.x + a.x * inv;
        r.y = 2.0f * f.y + a.y * inv;
        r.z = 2.0f * f.z + a.z * inv;
        r.w = 2.0f * f.w + a.w * inv;
    } else r = f;
    out[i] = r;
}

// ---------------------------------------------------------------------------
extern "C" void kernel_launch(void* const* d_in, const int* in_sizes, int n_in,
                              void* d_out, int out_size) {
    // Role selection by element count (dtype-independent):
    //   node_features: 6,400,000 elements (== out_size); edge_index: 2*E
    int nf_i = (in_sizes[0] == out_size) ? 0 : 1;
    int ei_i = 1 - nf_i;

    const float4* nf  = (const float4*)d_in[nf_i];
    const void*   ei  = d_in[ei_i];
    float4*       out = (float4*)d_out;
    int E = in_sizes[ei_i] / 2;

    prep_kernel<<<(N_NODES + 255) / 256, 256>>>((const long long*)ei, E);

    if (E <= E_MAX) {
        int eb = (E + 255) / 256;
        hist_kernel<<<eb, 256>>>(ei, E);
        scanA_kernel<<<NBLK, SCAN_B>>>();
        scanB_kernel<<<NBLK, SCAN_B>>>();
        scatter_kernel<<<eb, 256>>>(ei, E);
        aggregate_kernel<<<(NTOT4 + 255) / 256, 256>>>(nf, out);
    } else {
        fb_zero_kernel<<<(NTOT4 + 255) / 256, 256>>>(out);
        long long total = (long long)E * 16;
        fb_edge_kernel<<<(int)((total + 255) / 256), 256>>>(nf, ei, out, E);
        fb_final_kernel<<<(NTOT4 + 255) / 256, 256>>>(nf, out);
    }
}

// round 16
// speedup vs baseline: 3.5990x; 1.2196x over previous
#include <cuda_runtime.h>
#include <stdint.h>

#define N_NODES 100000
#define F4      16                       // 64 floats = 16 float4 per node
#define NTOT4   (N_NODES * F4)
#define CAP     64                       // bucket capacity (deg ~ Poisson(16))
#define E_MAX   2000000                  // overflow list capacity

// Scratch (no device allocation allowed -> __device__ globals)
__device__ int g_counts[N_NODES];            // in-degree (true count)
__device__ int g_bucket[N_NODES * CAP];      // src ids, bucketized by dst
__device__ int g_ovf[2 * E_MAX];             // overflow (s,d) pairs
__device__ int g_ovf_n;                      // overflow count
__device__ int g_idx_is64;                   // 1 = int64 indices, 0 = int32

// ---------------------------------------------------------------------------
// A: zero counts + overflow counter + dtype detect (64 batched loads).
// int32 data read as int64 packs two indices: value >= 2^32 unless the high
// index is 0 (p = 1e-5 per word) -> 64 words decide essentially surely.
// ---------------------------------------------------------------------------
__global__ void prep_kernel(const long long* __restrict__ ei, int E) {
    int i = blockIdx.x * blockDim.x + threadIdx.x;
    if (i < N_NODES) g_counts[i] = 0;
    if (blockIdx.x == 0 && threadIdx.x == 0) {
        g_ovf_n = 0;
        int n = E < 64 ? E : 64;
        int ok = 1;
        #pragma unroll
        for (int k = 0; k < 64; k++) {
            if (k < n) {
                long long v = ei[k];
                if (v < 0 || v >= N_NODES) ok = 0;
            }
        }
        g_idx_is64 = ok;
    }
}

// ---------------------------------------------------------------------------
// B: fused hist+scatter. One atomic per edge claims a bucket slot AND counts
// the in-degree (replaces hist + 2-launch scan + cursor scatter: one per-edge
// atomic pass instead of two, three fewer launches). Overflow (pos >= CAP)
// goes to an exact fixup list. 2 edges per thread: 16B index loads, 2x MLP
// on the latency-bound atomic chains.
// ---------------------------------------------------------------------------
__device__ __forceinline__ void scatter_one(long long s, long long d) {
    if ((unsigned long long)s >= (unsigned long long)N_NODES ||
        (unsigned long long)d >= (unsigned long long)N_NODES) return;
    int di  = (int)d;
    int pos = atomicAdd(&g_counts[di], 1);
    if (pos < CAP) {
        g_bucket[di * CAP + pos] = (int)s;
    } else {
        int o = atomicAdd(&g_ovf_n, 1);
        if (o < E_MAX) { g_ovf[2 * o] = (int)s; g_ovf[2 * o + 1] = di; }
    }
}

__global__ void scatter_kernel(const void* __restrict__ eiv, int E) {
    int t = blockIdx.x * blockDim.x + threadIdx.x;
    int p = 2 * t;                       // edge pair (p, p+1)
    if (p >= E) return;
    long long s0, d0, s1 = -1, d1 = -1;
    bool two = (p + 1 < E);
    if (g_idx_is64) {
        const long long* ei = (const long long*)eiv;
        if (two) {
            longlong2 sp = *(const longlong2*)&ei[p];
            longlong2 dp = *(const longlong2*)&ei[E + p];
            s0 = sp.x; s1 = sp.y; d0 = dp.x; d1 = dp.y;
        } else { s0 = ei[p]; d0 = ei[E + p]; }
    } else {
        const int* ei = (const int*)eiv;
        if (two) {
            int2 sp = *(const int2*)&ei[p];
            int2 dp = *(const int2*)&ei[E + p];
            s0 = sp.x; s1 = sp.y; d0 = dp.x; d1 = dp.y;
        } else { s0 = ei[p]; d0 = ei[E + p]; }
    }
    scatter_one(s0, d0);
    if (two) scatter_one(s1, d1);
}

// ---------------------------------------------------------------------------
// C: aggregate + finalize, fused. 16 lanes per node, lane c owns float4 #c.
// Batch-load 16 src ids coalesced (64B per group), shfl-broadcast within the
// 16-lane segment; unrolled LDG chain raises MLP into the L2-resident table.
//   out[i] = cnt>0 ? 2*nf[i] + sum_src/cnt : nf[i]
// Sums the bucketized entries (min(cnt,CAP)); overflow handled by fixup.
// Output written exactly once by this kernel.
// ---------------------------------------------------------------------------
__global__ void aggregate_kernel(const float4* __restrict__ nf,
                                 float4* __restrict__ out) {
    int t = blockIdx.x * blockDim.x + threadIdx.x;
    int node = t >> 4;
    int c    = t & 15;
    if (node >= N_NODES) return;
    unsigned gmask = 0xFFFFu << (threadIdx.x & 16);

    int row = node * CAP;
    int cnt = g_counts[node];
    int cb  = cnt < CAP ? cnt : CAP;     // entries present in the bucket

    float4 acc = make_float4(0.f, 0.f, 0.f, 0.f);
    int base = 0;
    int nfull = cb & ~15;                // full 16-edge batches
    for (; base < nfull; base += 16) {
        int id = g_bucket[row + base + c];
        #pragma unroll 4
        for (int j = 0; j < 16; j++) {
            int s = __shfl_sync(gmask, id, j, 16);
            float4 v = __ldg(&nf[(long long)s * F4 + c]);
            acc.x += v.x; acc.y += v.y; acc.z += v.z; acc.w += v.w;
        }
    }
    int m = cb - base;                   // 0..15 tail
    if (m > 0) {
        int k  = base + c;
        int id = (k < cb) ? g_bucket[row + k] : 0;
        for (int j = 0; j < m; j++) {
            int s = __shfl_sync(gmask, id, j, 16);
            float4 v = __ldg(&nf[(long long)s * F4 + c]);
            acc.x += v.x; acc.y += v.y; acc.z += v.z; acc.w += v.w;
        }
    }

    float4 f = nf[(long long)node * F4 + c];
    float4 r;
    if (cnt > 0) {
        float inv = 1.0f / (float)cnt;
        r.x = 2.0f * f.x + acc.x * inv;
        r.y = 2.0f * f.y + acc.y * inv;
        r.z = 2.0f * f.z + acc.z * inv;
        r.w = 2.0f * f.w + acc.w * inv;
    } else {
        r = f;
    }
    out[(long long)node * F4 + c] = r;
}

// ---------------------------------------------------------------------------
// D: exact overflow fixup. Grid-stride over g_ovf (16 lanes per entry):
//    out[d] += nf[s] / cnt[d] via vector RED. For the Poisson(16) input,
//    g_ovf_n == 0 and every thread exits after one cached load (~1.5 us).
// ---------------------------------------------------------------------------
__global__ void fixup_kernel(const float4* __restrict__ nf,
                             float4* __restrict__ out) {
    int n = g_ovf_n;
    if (n > E_MAX) n = E_MAX;
    if (n == 0) return;
    long long total = (long long)n * 16;
    long long stride = (long long)gridDim.x * blockDim.x;
    for (long long t = (long long)blockIdx.x * blockDim.x + threadIdx.x;
         t < total; t += stride) {
        int e = (int)(t >> 4);
        int c = (int)(t & 15);
        int s = g_ovf[2 * e];
        int d = g_ovf[2 * e + 1];
        float inv = 1.0f / (float)g_counts[d];
        float4 v = __ldg(&nf[(long long)s * F4 + c]);
        float4* p = &out[(long long)d * F4 + c];
        asm volatile("red.global.add.v4.f32 [%0], {%1, %2, %3, %4};"
                     :: "l"(p), "f"(v.x * inv), "f"(v.y * inv),
                        "f"(v.z * inv), "f"(v.w * inv) : "memory");
    }
}

// ---------------------------------------------------------------------------
extern "C" void kernel_launch(void* const* d_in, const int* in_sizes, int n_in,
                              void* d_out, int out_size) {
    // Role selection by element count (dtype-independent):
    //   node_features: 6,400,000 elements (== out_size); edge_index: 2*E
    int nf_i = (in_sizes[0] == out_size) ? 0 : 1;
    int ei_i = 1 - nf_i;

    const float4* nf  = (const float4*)d_in[nf_i];
    const void*   ei  = d_in[ei_i];
    float4*       out = (float4*)d_out;
    int E = in_sizes[ei_i] / 2;

    prep_kernel<<<(N_NODES + 255) / 256, 256>>>((const long long*)ei, E);

    int pairs = (E + 1) / 2;
    scatter_kernel<<<(pairs + 255) / 256, 256>>>(ei, E);

    aggregate_kernel<<<(NTOT4 + 255) / 256, 256>>>(nf, out);

    fixup_kernel<<<1184, 256>>>(nf, out);
}